// round 14
// baseline (speedup 1.0000x reference)
#include <cuda_runtime.h>
#include <cuda_bf16.h>
#include <math.h>

#define BB 8
#define TT 1024
#define DD 1024
#define HH 16
#define AD 64
#define BT (BB*TT)      /* 8192 */
#define HA (HH*AD)      /* 1024 */
#define KP2 (DD/2)      /* 512 k-pairs */
#define NEDGE 262144
#define BIASDIM 32
#define FBIG 3.402823466e+38f

// ---------------- scratch (no allocations allowed) ----------------
__device__ float g_v[BT*HA];
__device__ float g_ksum[BT*HH];        // [bt][h]
__device__ float g_bs[BB*TT*TT];
__device__ int   g_winner[BB*TT*TT];
__device__ float g_alpha[(size_t)BB*HH*TT*TT];
__device__ float2 g_rowstat[BB*HH*TT];  // (rowmax, 1/sum)
__device__ float g_proj[BIASDIM];
__device__ int   g_is64;
// packed bf16 hi/lo operand buffers
__device__ unsigned g_sth[BT*KP2], g_stl[BT*KP2];     // states   (A-pack, pairs along d)
__device__ unsigned g_kth[BT*KP2], g_ktl[BT*KP2];     // key_states
__device__ unsigned g_ctxh[BT*KP2], g_ctxl[BT*KP2];   // ctx      (pairs along ha)
__device__ unsigned g_qph[BT*KP2], g_qpl[BT*KP2];     // q        (pairs along a)
__device__ unsigned g_kph[BT*KP2], g_kpl[BT*KP2];     // k        (pairs along a)
__device__ unsigned g_wh[4][KP2*HA], g_wl[4][KP2*HA]; // weights (B-pack, vertical pairs): 0=Wq 1=Wk 2=Wv 3=Wout

// ---------------- bf16 split helpers ----------------
__device__ __forceinline__ unsigned pack2bf(float x0, float x1, float& r0, float& r1) {
    __nv_bfloat16 b0 = __float2bfloat16_rn(x0), b1 = __float2bfloat16_rn(x1);
    r0 = x0 - __bfloat162float(b0);
    r1 = x1 - __bfloat162float(b1);
    return ((unsigned)__bfloat16_as_ushort(b1) << 16) | (unsigned)__bfloat16_as_ushort(b0);
}
__device__ __forceinline__ unsigned pack2bf_o(float x0, float x1) {
    unsigned r; asm("cvt.rn.bf16x2.f32 %0, %1, %2;" : "=r"(r) : "f"(x1), "f"(x0)); return r;
}
__device__ __forceinline__ void mma_bf16(float (&d)[4], const unsigned (&a)[4],
                                         const unsigned (&b)[2]) {
    asm("mma.sync.aligned.m16n8k16.row.col.f32.bf16.bf16.f32 "
        "{%0,%1,%2,%3}, {%4,%5,%6,%7}, {%8,%9}, {%0,%1,%2,%3};"
        : "+f"(d[0]), "+f"(d[1]), "+f"(d[2]), "+f"(d[3])
        : "r"(a[0]), "r"(a[1]), "r"(a[2]), "r"(a[3]), "r"(b[0]), "r"(b[1]));
}

// ---------------- fast exp (FMA-only, for x <= 0) ----------------
__device__ __forceinline__ float fexp(float x) {
    float y = fmaxf(x * 1.4426950408889634f, -126.0f);
    int   i = __float2int_rn(y);
    float f = y - (float)i;
    float p = 1.5403530e-4f;
    p = fmaf(p, f, 1.3333558e-3f);
    p = fmaf(p, f, 9.6181291e-3f);
    p = fmaf(p, f, 5.5504109e-2f);
    p = fmaf(p, f, 2.4022651e-1f);
    p = fmaf(p, f, 6.9314718e-1f);
    p = fmaf(p, f, 1.0f);
    return p * __int_as_float((i + 127) << 23);
}

// ---------------- pre-pack kernels ----------------
// A-style: X[M][K] -> Xh/Xl[M][K/2], pair = (X[m][2p], X[m][2p+1])
__global__ void packA_kernel(const float* __restrict__ X, int which) {
    unsigned* Xh = (which == 0) ? g_sth : g_kth;
    unsigned* Xl = (which == 0) ? g_stl : g_ktl;
    int i = blockIdx.x * blockDim.x + threadIdx.x;   // float4 units
    if (i >= BT * DD / 4) return;
    float4 v = ((const float4*)X)[i];
    float l0, l1, l2, l3;
    unsigned h0 = pack2bf(v.x, v.y, l0, l1);
    unsigned h1 = pack2bf(v.z, v.w, l2, l3);
    ((uint2*)Xh)[i] = make_uint2(h0, h1);
    ((uint2*)Xl)[i] = make_uint2(pack2bf_o(l0, l1), pack2bf_o(l2, l3));
}
// B-style: W[K][N] -> Wh/Wl[K/2][N], pair = (W[2p][n], W[2p+1][n])
__global__ void packB_kernel(const float* __restrict__ W, int which) {
    int i = blockIdx.x * blockDim.x + threadIdx.x;   // uint4 units over KP2*HA/4
    if (i >= KP2 * HA / 4) return;
    int p  = i >> 8;                // HA/4 = 256 uint4 per packed row
    int n4 = (i & 255) * 4;
    const float* r0p = W + (size_t)(2 * p) * HA + n4;
    float4 a = *(const float4*)r0p;
    float4 b = *(const float4*)(r0p + HA);
    float l0, l1, l2, l3, l4, l5, l6, l7;
    unsigned h0 = pack2bf(a.x, b.x, l0, l1);
    unsigned h1 = pack2bf(a.y, b.y, l2, l3);
    unsigned h2 = pack2bf(a.z, b.z, l4, l5);
    unsigned h3 = pack2bf(a.w, b.w, l6, l7);
    *(uint4*)&g_wh[which][(size_t)p * HA + n4] = make_uint4(h0, h1, h2, h3);
    *(uint4*)&g_wl[which][(size_t)p * HA + n4] =
        make_uint4(pack2bf_o(l0, l1), pack2bf_o(l2, l3),
                   pack2bf_o(l4, l5), pack2bf_o(l6, l7));
}

// ---------------- dtype detector for attention_bias ----------------
__global__ void detect_kernel(const int* __restrict__ ab32) {
    int ok = 1;
    #pragma unroll
    for (int i = 0; i < 64; i++) ok &= (ab32[2 * i + 1] == 0);
    g_is64 = ok;
}

// ---------------- proj[et] = bias_embs[et] . bias_scalar ----------------
__global__ void proj_kernel(const float* __restrict__ embs, const float* __restrict__ scal) {
    int et = threadIdx.x;
    if (et >= BIASDIM) return;
    float s = 0.f;
    #pragma unroll
    for (int a = 0; a < AD; a++) s += embs[et * AD + a] * scal[a];
    g_proj[et] = s;
}

// ---------------- BF16 GEMM on pre-packed operands ----------------
// which_a: 0=states, 1=key_states, 2=ctx.  which_b: weight index 0..3.
// which_c: 0=packed q, 1=packed k, 2=f32 g_v, 3=f32 Cext.
__global__ __launch_bounds__(256, 2)
void bf16_gemm_kernel(float* __restrict__ Cext, int which_a, int which_b, int which_c,
                      int M, int N, int K) {
    const unsigned* Aph = (which_a == 0) ? g_sth : (which_a == 1) ? g_kth : g_ctxh;
    const unsigned* Apl = (which_a == 0) ? g_stl : (which_a == 1) ? g_ktl : g_ctxl;
    const unsigned* Bph = g_wh[which_b];
    const unsigned* Bpl = g_wl[which_b];
    const int KPP = K / 2;
    __shared__ unsigned Ahp[8][136], Alp[8][136];   // [kpair][m]
    __shared__ unsigned Bhp[8][136], Blp[8][136];   // [kpair][n]
    const int tid = threadIdx.x;
    const int wid = tid >> 5, lane = tid & 31;
    const int g = lane >> 2, tq = lane & 3;
    const int warp_m = wid >> 1, warp_n = wid & 1;
    const int m0 = blockIdx.y * 128, n0 = blockIdx.x * 128;

    float acc[2][8][4];
    #pragma unroll
    for (int mf = 0; mf < 2; mf++)
        #pragma unroll
        for (int nf = 0; nf < 8; nf++)
            #pragma unroll
            for (int r = 0; r < 4; r++) acc[mf][nf][r] = 0.f;

    for (int k0p = 0; k0p < KPP; k0p += 8) {
        // stage A (copy): 128 rows x 8 kpairs
        {
            int row = tid >> 1, kp4 = (tid & 1) * 4;
            size_t base = (size_t)(m0 + row) * KPP + k0p + kp4;
            uint4 h = *(const uint4*)&Aph[base];
            uint4 l = *(const uint4*)&Apl[base];
            Ahp[kp4 + 0][row] = h.x; Ahp[kp4 + 1][row] = h.y;
            Ahp[kp4 + 2][row] = h.z; Ahp[kp4 + 3][row] = h.w;
            Alp[kp4 + 0][row] = l.x; Alp[kp4 + 1][row] = l.y;
            Alp[kp4 + 2][row] = l.z; Alp[kp4 + 3][row] = l.w;
        }
        // stage B (copy): 8 kpairs x 128 cols
        {
            int p = tid >> 5, ng = (tid & 31) * 4;
            size_t base = (size_t)(k0p + p) * N + n0 + ng;
            *(uint4*)&Bhp[p][ng] = *(const uint4*)&Bph[base];
            *(uint4*)&Blp[p][ng] = *(const uint4*)&Bpl[base];
        }
        __syncthreads();

        unsigned afh[2][4], afl[2][4];
        #pragma unroll
        for (int mf = 0; mf < 2; mf++) {
            int mr = warp_m * 32 + mf * 16 + g;
            afh[mf][0] = Ahp[tq][mr];     afh[mf][1] = Ahp[tq][mr + 8];
            afh[mf][2] = Ahp[tq + 4][mr]; afh[mf][3] = Ahp[tq + 4][mr + 8];
            afl[mf][0] = Alp[tq][mr];     afl[mf][1] = Alp[tq][mr + 8];
            afl[mf][2] = Alp[tq + 4][mr]; afl[mf][3] = Alp[tq + 4][mr + 8];
        }
        #pragma unroll
        for (int nf = 0; nf < 8; nf++) {
            int nc = warp_n * 64 + nf * 8 + g;
            unsigned bh[2] = { Bhp[tq][nc], Bhp[tq + 4][nc] };
            unsigned bl[2] = { Blp[tq][nc], Blp[tq + 4][nc] };
            #pragma unroll
            for (int mf = 0; mf < 2; mf++) {
                mma_bf16(acc[mf][nf], afh[mf], bh);
                mma_bf16(acc[mf][nf], afh[mf], bl);
                mma_bf16(acc[mf][nf], afl[mf], bh);
            }
        }
        __syncthreads();
    }

    #pragma unroll
    for (int mf = 0; mf < 2; mf++) {
        int row0 = m0 + warp_m * 32 + mf * 16 + g;
        #pragma unroll
        for (int nf = 0; nf < 8; nf++) {
            int col = n0 + warp_n * 64 + nf * 8 + 2 * tq;
            if (which_c == 3) {
                *(float2*)&Cext[(size_t)row0 * N + col] =
                    make_float2(acc[mf][nf][0], acc[mf][nf][1]);
                *(float2*)&Cext[(size_t)(row0 + 8) * N + col] =
                    make_float2(acc[mf][nf][2], acc[mf][nf][3]);
            } else if (which_c == 2) {
                *(float2*)&g_v[(size_t)row0 * N + col] =
                    make_float2(acc[mf][nf][0], acc[mf][nf][1]);
                *(float2*)&g_v[(size_t)(row0 + 8) * N + col] =
                    make_float2(acc[mf][nf][2], acc[mf][nf][3]);
            } else {
                unsigned* Ch = (which_c == 0) ? g_qph : g_kph;
                unsigned* Cl = (which_c == 0) ? g_qpl : g_kpl;
                float l0, l1;
                unsigned h0 = pack2bf(acc[mf][nf][0], acc[mf][nf][1], l0, l1);
                Ch[(size_t)row0 * KP2 + (col >> 1)] = h0;
                Cl[(size_t)row0 * KP2 + (col >> 1)] = pack2bf_o(l0, l1);
                unsigned h1 = pack2bf(acc[mf][nf][2], acc[mf][nf][3], l0, l1);
                Ch[(size_t)(row0 + 8) * KP2 + (col >> 1)] = h1;
                Cl[(size_t)(row0 + 8) * KP2 + (col >> 1)] = pack2bf_o(l0, l1);
            }
        }
    }
}

// ---------------- ksum[bt][h] = sum_a k[b,t,h,a]  (from packed k) -----------
__global__ void ksum_kernel() {
    int idx = blockIdx.x * blockDim.x + threadIdx.x;   // bt*H + h
    if (idx >= BT * HH) return;
    int bt = idx / HH, h = idx % HH;
    const uint4* ph = (const uint4*)&g_kph[(size_t)bt * KP2 + h * 32];
    const uint4* pl = (const uint4*)&g_kpl[(size_t)bt * KP2 + h * 32];
    float s = 0.f;
    #pragma unroll
    for (int i = 0; i < 8; i++) {
        uint4 uh = ph[i], ul = pl[i];
        unsigned uu[8] = { uh.x, uh.y, uh.z, uh.w, ul.x, ul.y, ul.z, ul.w };
        #pragma unroll
        for (int j = 0; j < 8; j++) {
            float2 f = __bfloat1622float2(*(__nv_bfloat162*)&uu[j]);
            s += f.x + f.y;
        }
    }
    g_ksum[idx] = s;
}

// ---------------- zero dense bias + winner scratch ----------------
__global__ void zero_bs_kernel() {
    int i = blockIdx.x * blockDim.x + threadIdx.x;
    if (i < BB * TT * TT / 4) {
        ((float4*)g_bs)[i] = make_float4(0.f, 0.f, 0.f, 0.f);
        ((int4*)g_winner)[i] = make_int4(-1, -1, -1, -1);
    }
}

// ---------------- decode edge e ----------------
__device__ __forceinline__ bool decode_edge(const int* __restrict__ ab32, int e,
                                            int& et, int& b, int& qi, int& ki) {
    if (g_is64) {
        const long long* ab = (const long long*)ab32;
        et = (int)ab[4 * e + 0]; b  = (int)ab[4 * e + 1];
        qi = (int)ab[4 * e + 2]; ki = (int)ab[4 * e + 3];
    } else {
        et = ab32[4 * e + 0]; b  = ab32[4 * e + 1];
        qi = ab32[4 * e + 2]; ki = ab32[4 * e + 3];
    }
    return !((unsigned)et >= BIASDIM || (unsigned)b >= BB ||
             (unsigned)qi >= TT || (unsigned)ki >= TT);
}

__global__ void scatter_pass1_kernel(const int* __restrict__ ab32) {
    int e = blockIdx.x * blockDim.x + threadIdx.x;
    if (e >= NEDGE) return;
    int et, b, qi, ki;
    if (!decode_edge(ab32, e, et, b, qi, ki)) return;
    atomicMax(&g_winner[((size_t)b * TT + qi) * TT + ki], e);
}

__global__ void scatter_pass2_kernel(const int* __restrict__ ab32) {
    int e = blockIdx.x * blockDim.x + threadIdx.x;
    if (e >= NEDGE) return;
    int et, b, qi, ki;
    if (!decode_edge(ab32, e, et, b, qi, ki)) return;
    size_t slot = ((size_t)b * TT + qi) * TT + ki;
    if (g_winner[slot] == e) g_bs[slot] = g_proj[et];
}

// ---------------- scores BF16 (packed q/k): alpha = (QK^T + bs*ksum)*0.125 - mask*BIG
__global__ __launch_bounds__(256, 2)
void scores_bf16_kernel(const float* __restrict__ masks) {
    __shared__ unsigned Ahp[8][136], Alp[8][136];   // Q: [apair][q]
    __shared__ unsigned Bhp[8][136], Blp[8][136];   // K: [apair][k]
    __shared__ float ks_s[128];
    const int z = blockIdx.z;                 // b*H + h
    const int b = z >> 4, h = z & 15;
    const int q0 = blockIdx.y * 128, k0c = blockIdx.x * 128;
    const int tid = threadIdx.x;
    const int wid = tid >> 5, lane = tid & 31;
    const int g = lane >> 2, tq = lane & 3;
    const int warp_m = wid >> 1, warp_n = wid & 1;
    if (tid < 128) ks_s[tid] = g_ksum[(size_t)(b * TT + k0c + tid) * HH + h];

    float acc[2][8][4];
    #pragma unroll
    for (int mf = 0; mf < 2; mf++)
        #pragma unroll
        for (int nf = 0; nf < 8; nf++)
            #pragma unroll
            for (int r = 0; r < 4; r++) acc[mf][nf][r] = 0.f;

    #pragma unroll
    for (int a0p = 0; a0p < 32; a0p += 8) {
        // copy-stage Q and K tiles (128 rows x 8 apairs each)
        {
            int row = tid >> 1, pp = (tid & 1) * 4;
            size_t qb = (size_t)(b * TT + q0  + row) * KP2 + h * 32 + a0p + pp;
            size_t kb = (size_t)(b * TT + k0c + row) * KP2 + h * 32 + a0p + pp;
            uint4 qh = *(const uint4*)&g_qph[qb];
            uint4 ql = *(const uint4*)&g_qpl[qb];
            uint4 kh = *(const uint4*)&g_kph[kb];
            uint4 kl = *(const uint4*)&g_kpl[kb];
            Ahp[pp + 0][row] = qh.x; Ahp[pp + 1][row] = qh.y;
            Ahp[pp + 2][row] = qh.z; Ahp[pp + 3][row] = qh.w;
            Alp[pp + 0][row] = ql.x; Alp[pp + 1][row] = ql.y;
            Alp[pp + 2][row] = ql.z; Alp[pp + 3][row] = ql.w;
            Bhp[pp + 0][row] = kh.x; Bhp[pp + 1][row] = kh.y;
            Bhp[pp + 2][row] = kh.z; Bhp[pp + 3][row] = kh.w;
            Blp[pp + 0][row] = kl.x; Blp[pp + 1][row] = kl.y;
            Blp[pp + 2][row] = kl.z; Blp[pp + 3][row] = kl.w;
        }
        __syncthreads();
        unsigned afh[2][4], afl[2][4];
        #pragma unroll
        for (int mf = 0; mf < 2; mf++) {
            int mr = warp_m * 32 + mf * 16 + g;
            afh[mf][0] = Ahp[tq][mr];     afh[mf][1] = Ahp[tq][mr + 8];
            afh[mf][2] = Ahp[tq + 4][mr]; afh[mf][3] = Ahp[tq + 4][mr + 8];
            afl[mf][0] = Alp[tq][mr];     afl[mf][1] = Alp[tq][mr + 8];
            afl[mf][2] = Alp[tq + 4][mr]; afl[mf][3] = Alp[tq + 4][mr + 8];
        }
        #pragma unroll
        for (int nf = 0; nf < 8; nf++) {
            int nc = warp_n * 64 + nf * 8 + g;
            unsigned bh[2] = { Bhp[tq][nc], Bhp[tq + 4][nc] };
            unsigned bl[2] = { Blp[tq][nc], Blp[tq + 4][nc] };
            #pragma unroll
            for (int mf = 0; mf < 2; mf++) {
                mma_bf16(acc[mf][nf], afh[mf], bh);
                mma_bf16(acc[mf][nf], afh[mf], bl);
                mma_bf16(acc[mf][nf], afl[mf], bh);
            }
        }
        __syncthreads();
    }

    #pragma unroll
    for (int mf = 0; mf < 2; mf++) {
        int row0 = q0 + warp_m * 32 + mf * 16 + g;
        #pragma unroll
        for (int nf = 0; nf < 8; nf++) {
            int lc  = warp_n * 64 + nf * 8 + 2 * tq;
            int col = k0c + lc;
            float ka = ks_s[lc], kb = ks_s[lc + 1];
            #pragma unroll
            for (int r = 0; r < 2; r++) {
                int qi = row0 + r * 8;
                size_t rowbm = ((size_t)b * TT + qi) * TT + col;
                float2 bs2 = *(const float2*)&g_bs[rowbm];
                float2 mk2 = *(const float2*)&masks[rowbm];
                float v0 = (acc[mf][nf][2 * r]     + bs2.x * ka) * 0.125f - mk2.x * FBIG;
                float v1 = (acc[mf][nf][2 * r + 1] + bs2.y * kb) * 0.125f - mk2.y * FBIG;
                *(float2*)&g_alpha[((size_t)z * TT + qi) * TT + col] = make_float2(v0, v1);
            }
        }
    }
}

// ---------------- rowstat: per row, (max, 1/sum(exp(x-max))) -------------------
__global__ void rowstat_kernel() {
    __shared__ float smax[8];
    __shared__ float ssum[8];
    const float4* p = (const float4*)(g_alpha + (size_t)blockIdx.x * TT);
    const int tid = threadIdx.x;                 // 256
    const int lane = tid & 31, wid = tid >> 5;
    float4 x = p[tid];
    float mx = fmaxf(fmaxf(x.x, x.y), fmaxf(x.z, x.w));
    #pragma unroll
    for (int o = 16; o; o >>= 1) mx = fmaxf(mx, __shfl_xor_sync(0xffffffffu, mx, o));
    if (lane == 0) smax[wid] = mx;
    __syncthreads();
    mx = smax[0];
    #pragma unroll
    for (int w = 1; w < 8; w++) mx = fmaxf(mx, smax[w]);
    float s = fexp(x.x - mx) + fexp(x.y - mx) + fexp(x.z - mx) + fexp(x.w - mx);
    #pragma unroll
    for (int o = 16; o; o >>= 1) s += __shfl_xor_sync(0xffffffffu, s, o);
    if (lane == 0) ssum[wid] = s;
    __syncthreads();
    if (tid == 0) {
        float tot = 0.f;
        #pragma unroll
        for (int w = 0; w < 8; w++) tot += ssum[w];
        g_rowstat[blockIdx.x] = make_float2(mx, 1.0f / tot);
    }
}

// ---------------- context BF16 + fused softmax normalize, packed ctx out --------
__global__ __launch_bounds__(256, 2)
void context_bf16_kernel() {
    __shared__ unsigned Ahp[8][136], Alp[8][136];   // P: [kpair][q]
    __shared__ unsigned Bhp[8][72],  Blp[8][72];    // V: [kpair][a]
    __shared__ float2 rs_s[128];
    const int z = blockIdx.y;                 // b*H + h
    const int b = z >> 4, h = z & 15;
    const int q0 = blockIdx.x * 128;
    const int tid = threadIdx.x;
    const int wid = tid >> 5, lane = tid & 31;
    const int g = lane >> 2, tq = lane & 3;
    const int warp_m = wid >> 1, warp_n = wid & 1;
    const float* arow  = g_alpha + ((size_t)z * TT + q0) * TT;
    const float* vbase = g_v + (size_t)(b * TT) * HA + h * AD;
    if (tid < 128) rs_s[tid] = g_rowstat[(size_t)z * TT + q0 + tid];
    __syncthreads();

    float acc[2][4][4];
    #pragma unroll
    for (int mf = 0; mf < 2; mf++)
        #pragma unroll
        for (int nf = 0; nf < 4; nf++)
            #pragma unroll
            for (int r = 0; r < 4; r++) acc[mf][nf][r] = 0.f;

    for (int k0 = 0; k0 < TT; k0 += 16) {
        // stage P 128x16 : p = exp(alpha - mx)
        #pragma unroll
        for (int it = 0; it < 2; it++) {
            int idx = tid + it * 256;           // 0..511
            int row = idx >> 2, kg = (idx & 3) * 4, kp = kg >> 1;
            float mx = rs_s[row].x;
            float4 v = *(const float4*)&arow[(size_t)row * TT + k0 + kg];
            float p0 = fexp(v.x - mx), p1 = fexp(v.y - mx);
            float p2 = fexp(v.z - mx), p3 = fexp(v.w - mx);
            float l0, l1, l2, l3;
            Ahp[kp][row]     = pack2bf(p0, p1, l0, l1);
            Ahp[kp + 1][row] = pack2bf(p2, p3, l2, l3);
            Alp[kp][row]     = pack2bf_o(l0, l1);
            Alp[kp + 1][row] = pack2bf_o(l2, l3);
        }
        // stage V 16x64: vertical pack across two k-rows
        {
            int kp = tid >> 5, ng = (tid & 31) * 2;
            const float* vp = &vbase[(size_t)(k0 + 2 * kp) * HA + ng];
            float2 r0 = *(const float2*)vp;
            float2 r1 = *(const float2*)(vp + HA);
            float a0, a1, a2, a3;
            unsigned h0 = pack2bf(r0.x, r1.x, a0, a1);
            unsigned h1 = pack2bf(r0.y, r1.y, a2, a3);
            Bhp[kp][ng] = h0;     Bhp[kp][ng + 1] = h1;
            Blp[kp][ng] = pack2bf_o(a0, a1);
            Blp[kp][ng + 1] = pack2bf_o(a2, a3);
        }
        __syncthreads();
        unsigned afh[2][4], afl[2][4];
        #pragma unroll
        for (int mf = 0; mf < 2; mf++) {
            int mr = warp_m * 32 + mf * 16 + g;
            afh[mf][0] = Ahp[tq][mr];     afh[mf][1] = Ahp[tq][mr + 8];
            afh[mf][2] = Ahp[tq + 4][mr]; afh[mf][3] = Ahp[tq + 4][mr + 8];
            afl[mf][0] = Alp[tq][mr];     afl[mf][1] = Alp[tq][mr + 8];
            afl[mf][2] = Alp[tq + 4][mr]; afl[mf][3] = Alp[tq + 4][mr + 8];
        }
        #pragma unroll
        for (int nf = 0; nf < 4; nf++) {
            int nc = warp_n * 32 + nf * 8 + g;
            unsigned bh[2] = { Bhp[tq][nc], Bhp[tq + 4][nc] };
            unsigned bl[2] = { Blp[tq][nc], Blp[tq + 4][nc] };
            #pragma unroll
            for (int mf = 0; mf < 2; mf++) {
                mma_bf16(acc[mf][nf], afh[mf], bh);
                mma_bf16(acc[mf][nf], afh[mf], bl);
                mma_bf16(acc[mf][nf], afl[mf], bh);
            }
        }
        __syncthreads();
    }

    // epilogue: normalize and write PACKED ctx (pairs along a == out-proj kpairs)
    #pragma unroll
    for (int mf = 0; mf < 2; mf++) {
        int lr0 = warp_m * 32 + mf * 16 + g;
        float inv0 = rs_s[lr0].y, inv1 = rs_s[lr0 + 8].y;
        int row0 = q0 + lr0;
        #pragma unroll
        for (int nf = 0; nf < 4; nf++) {
            int col = warp_n * 32 + nf * 8 + 2 * tq;     // within-head a, even
            size_t i0 = (size_t)(b * TT + row0) * KP2 + h * 32 + (col >> 1);
            size_t i1 = (size_t)(b * TT + row0 + 8) * KP2 + h * 32 + (col >> 1);
            float l0, l1;
            unsigned h0 = pack2bf(acc[mf][nf][0] * inv0, acc[mf][nf][1] * inv0, l0, l1);
            g_ctxh[i0] = h0; g_ctxl[i0] = pack2bf_o(l0, l1);
            unsigned h1 = pack2bf(acc[mf][nf][2] * inv1, acc[mf][nf][3] * inv1, l0, l1);
            g_ctxh[i1] = h1; g_ctxl[i1] = pack2bf_o(l0, l1);
        }
    }
}

// ---------------- launch ----------------
extern "C" void kernel_launch(void* const* d_in, const int* in_sizes, int n_in,
                              void* d_out, int out_size) {
    const float* states     = (const float*)d_in[0];
    const float* key_states = (const float*)d_in[1];
    const float* masks      = (const float*)d_in[2];
    const int*   ab32       = (const int*)d_in[3];
    const float* Wq         = (const float*)d_in[4];
    const float* Wk         = (const float*)d_in[5];
    const float* Wv         = (const float*)d_in[6];
    const float* Wout       = (const float*)d_in[7];
    const float* embs       = (const float*)d_in[8];
    const float* scal       = (const float*)d_in[9];
    float* out              = (float*)d_out;

    // pre-pack operands
    packA_kernel<<<BT * DD / 4 / 256, 256>>>(states, 0);
    packA_kernel<<<BT * DD / 4 / 256, 256>>>(key_states, 1);
    packB_kernel<<<KP2 * HA / 4 / 256, 256>>>(Wq, 0);
    packB_kernel<<<KP2 * HA / 4 / 256, 256>>>(Wk, 1);
    packB_kernel<<<KP2 * HA / 4 / 256, 256>>>(Wv, 2);
    packB_kernel<<<KP2 * HA / 4 / 256, 256>>>(Wout, 3);

    dim3 gemm_grid(HA / 128, BT / 128);   // (8, 64)

    // QKV projections (q,k write packed; v writes f32)
    bf16_gemm_kernel<<<gemm_grid, 256>>>(nullptr, 0, 0, 0, BT, HA, DD);
    bf16_gemm_kernel<<<gemm_grid, 256>>>(nullptr, 1, 1, 1, BT, HA, DD);
    bf16_gemm_kernel<<<gemm_grid, 256>>>(nullptr, 1, 2, 2, BT, HA, DD);

    // ksum (from packed k)
    ksum_kernel<<<(BT * HH + 255) / 256, 256>>>();

    // edge-bias detect + projection + deterministic scatter
    detect_kernel<<<1, 1>>>(ab32);
    proj_kernel<<<1, 32>>>(embs, scal);
    zero_bs_kernel<<<(BB * TT * TT / 4 + 255) / 256, 256>>>();
    scatter_pass1_kernel<<<(NEDGE + 255) / 256, 256>>>(ab32);
    scatter_pass2_kernel<<<(NEDGE + 255) / 256, 256>>>(ab32);

    // scores (packed q/k) + row stats
    dim3 sc_grid(TT / 128, TT / 128, BB * HH);   // (8, 8, 128)
    scores_bf16_kernel<<<sc_grid, 256>>>(masks);
    rowstat_kernel<<<BB * HH * TT, 256>>>();

    // context (fused exp-normalize, packed ctx out)
    dim3 cx_grid(TT / 128, BB * HH);             // (8, 128)
    context_bf16_kernel<<<cx_grid, 256>>>();

    // output projection (A = packed ctx, B = packed Wout, C = d_out f32)
    bf16_gemm_kernel<<<gemm_grid, 256>>>(out, 2, 3, 3, BT, DD, HA);
}